// round 8
// baseline (speedup 1.0000x reference)
#include <cuda_runtime.h>
#include <cuda_bf16.h>

// IoUMetricLoss: pred_label fp32 [8,19,512,1024], label int32 [8,512,1024]
// out: scalar fp32 = 1 - nanmean(IoU per class), all-NaN -> 0.5
//
// R8: cp.async (LDGSTS) double-buffered persistent pipeline.
// R4/R5/R7 proved warp-scoreboard LDG saturates at ~72% DRAM regardless of
// occupancy/MLP knobs. cp.async decouples load issue from registers and
// scoreboards: each thread keeps 20x16B copies in flight per stage and only
// blocks one stage behind at wait_group. 296 persistent CTAs (2/SM) x 128
// threads, 2 stages x 40KB smem, atomic-ticket tile scheduler (8192 tiles
// of 512 px), fused last-block finalize with full state reset.

#define NUM_CLASSES 19
#define HW_SHIFT 19                  // 512*1024 = 2^19
#define HW (1 << HW_SHIFT)
#define TOTAL_PIX (8 * HW)           // 4194304
#define T 128                        // threads per CTA
#define PIX_PER_TILE (T * 4)         // 512
#define NTILES (TOTAL_PIX / PIX_PER_TILE)   // 8192
#define NCTAS 296                    // 2 per SM x 148 SMs
#define NSLOTS (NUM_CLASSES + 1)     // 19 classes + label
#define SLOT_BYTES (T * 16)          // 2048
#define STAGE_BYTES (NSLOTS * SLOT_BYTES)   // 40960
#define SMEM_BYTES (2 * STAGE_BYTES)        // 81920

// Global state (no cudaMalloc allowed). Statically zero; the finalizing
// block resets everything so each graph replay sees clean state.
// g_li[c]: low 32 = area_label, high 32 = area_intersect.
__device__ unsigned long long g_li[NUM_CLASSES];
__device__ unsigned int       g_pred[NUM_CLASSES];
__device__ unsigned int       g_done;
__device__ unsigned int       g_ticket;

__device__ __forceinline__ unsigned smem_u32(const void* p) {
    return (unsigned)__cvta_generic_to_shared(p);
}
__device__ __forceinline__ void cp_async16(unsigned dst, const void* src) {
    asm volatile("cp.async.cg.shared.global [%0], [%1], 16;\n"
                 :: "r"(dst), "l"(src) : "memory");
}
__device__ __forceinline__ void amax_step(float v, float& bv, int& bi, int c) {
    float m = fmaxf(bv, v);
    bi = (v > bv) ? c : bi;
    bv = m;
}

__global__ void __launch_bounds__(T, 2)
iou_pipe_kernel(const float* __restrict__ pred,
                const int* __restrict__ label,
                float* __restrict__ out) {
    extern __shared__ unsigned char dynbuf[];
    __shared__ unsigned long long s_li[T / 32][NUM_CLASSES];
    __shared__ unsigned int       s_pr[T / 32][NUM_CLASSES];
    __shared__ int                s_tile[2];
    __shared__ int                s_is_last;

    const int tid  = threadIdx.x;
    const int warp = tid >> 5;
    const int lane = tid & 31;

    if (lane < NUM_CLASSES) {
        s_li[warp][lane] = 0ULL;
        s_pr[warp][lane] = 0u;
    }

    const unsigned sbase = smem_u32(dynbuf);

    // ---- fill: issue 20x16B cp.async for one tile into one stage ----
    auto fill = [&](int stage, int tile) {
        if (tile < NTILES) {
            const unsigned P  = (unsigned)tile * PIX_PER_TILE + tid * 4;
            const unsigned b  = P >> HW_SHIFT;
            const unsigned hw = P & (HW - 1);
            const float* base = pred + ((size_t)b * NUM_CLASSES << HW_SHIFT) + hw;
            const unsigned dst = sbase + (unsigned)stage * STAGE_BYTES + tid * 16;
            #pragma unroll
            for (int c = 0; c < NUM_CLASSES; c++)
                cp_async16(dst + c * SLOT_BYTES, base + ((size_t)c << HW_SHIFT));
            cp_async16(dst + NUM_CLASSES * SLOT_BYTES, label + P);
        }
        asm volatile("cp.async.commit_group;\n" ::: "memory");
    };

    // ---- prologue: fetch + start two tiles ----
    if (tid == 0) s_tile[0] = (int)atomicAdd(&g_ticket, 1u);
    __syncthreads();
    fill(0, s_tile[0]);
    if (tid == 0) s_tile[1] = (int)atomicAdd(&g_ticket, 1u);
    __syncthreads();
    fill(1, s_tile[1]);

    const float4* fbuf = (const float4*)dynbuf;
    const int4*   ibuf = (const int4*)dynbuf;

    int cur = 0;
    for (;;) {
        const int tile = s_tile[cur];
        if (tile >= NTILES) break;

        // wait for the oldest group (this stage's fill), then make visible
        asm volatile("cp.async.wait_group 1;\n" ::: "memory");
        __syncthreads();

        // ---- compute: argmax over 19 classes for this thread's 4 pixels ----
        const int sb = cur * NSLOTS * T + tid;   // float4 index of slot 0
        float4 bv = fbuf[sb];
        int i0 = 0, i1 = 0, i2 = 0, i3 = 0;
        #pragma unroll
        for (int c = 1; c < NUM_CLASSES; c++) {
            float4 v = fbuf[sb + c * T];
            amax_step(v.x, bv.x, i0, c);
            amax_step(v.y, bv.y, i1, c);
            amax_step(v.z, bv.z, i2, c);
            amax_step(v.w, bv.w, i3, c);
        }
        int4 lv = ibuf[sb + NUM_CLASSES * T];

        #define ACC(l, i)                                                      \
            if ((l) >= 0) {                                                    \
                atomicAdd(&s_li[warp][(l)],                                    \
                          1ULL | (((i) == (l)) ? (1ULL << 32) : 0ULL));        \
                atomicAdd(&s_pr[warp][(i)], 1u);                               \
            }
        ACC(lv.x, i0); ACC(lv.y, i1); ACC(lv.z, i2); ACC(lv.w, i3);
        #undef ACC

        // all threads done reading this stage before it is overwritten
        __syncthreads();
        if (tid == 0) s_tile[cur] = (int)atomicAdd(&g_ticket, 1u);
        __syncthreads();
        fill(cur, s_tile[cur]);
        cur ^= 1;
    }
    // drain (remaining groups are empty fills; hygiene only)
    asm volatile("cp.async.wait_group 0;\n" ::: "memory");
    __syncthreads();

    // ---- block reduce: one global atomic per class per counter ----
    if (tid < NUM_CLASSES) {
        unsigned long long li = 0ULL;
        unsigned int       pr = 0u;
        #pragma unroll
        for (int w = 0; w < T / 32; w++) {
            li += s_li[w][tid];
            pr += s_pr[w][tid];
        }
        atomicAdd(&g_li[tid], li);
        atomicAdd(&g_pred[tid], pr);
    }
    __syncthreads();

    // ---- last-block-done finalize + full state reset ----
    if (tid == 0) {
        __threadfence();
        unsigned prev = atomicAdd(&g_done, 1u);
        s_is_last = (prev == gridDim.x - 1);
    }
    __syncthreads();
    if (!s_is_last) return;

    if (tid < 32) {
        const int c = tid;
        float iou_sum = 0.0f;
        int   valid   = 0;
        if (c < NUM_CLASSES) {
            unsigned long long li = g_li[c];
            unsigned int pr    = g_pred[c];
            unsigned int lab   = (unsigned int)(li & 0xFFFFFFFFULL);
            unsigned int inter = (unsigned int)(li >> 32);
            unsigned long long uni =
                (unsigned long long)lab + (unsigned long long)pr
                - (unsigned long long)inter;
            if (uni > 0ULL) {
                iou_sum = (float)inter / (float)uni;
                valid   = 1;
            }
            // uni == 0 -> 0/0 = NaN in reference, excluded by nanmean
            g_li[c]   = 0ULL;   // reset for next graph replay
            g_pred[c] = 0u;
        }
        #pragma unroll
        for (int o = 16; o > 0; o >>= 1) {
            iou_sum += __shfl_down_sync(0xFFFFFFFFu, iou_sum, o);
            valid   += __shfl_down_sync(0xFFFFFFFFu, valid, o);
        }
        if (c == 0) {
            g_done   = 0u;
            g_ticket = 0u;
            float loss = (valid > 0) ? (1.0f - iou_sum / (float)valid) : 0.5f;
            *out = loss;
        }
    }
}

extern "C" void kernel_launch(void* const* d_in, const int* in_sizes, int n_in,
                              void* d_out, int out_size) {
    // pred = 79,691,776 elems; label = 4,194,304 (resolve by size).
    const float* pred;
    const int*   label;
    if (in_sizes[0] >= in_sizes[1]) {
        pred  = (const float*)d_in[0];
        label = (const int*)d_in[1];
    } else {
        pred  = (const float*)d_in[1];
        label = (const int*)d_in[0];
    }
    float* out = (float*)d_out;

    // 80KB dynamic smem needs the opt-in attribute (idempotent, graph-safe).
    cudaFuncSetAttribute(iou_pipe_kernel,
                         cudaFuncAttributeMaxDynamicSharedMemorySize,
                         SMEM_BYTES);

    iou_pipe_kernel<<<NCTAS, T, SMEM_BYTES>>>(pred, label, out);
}

// round 9
// speedup vs baseline: 1.0017x; 1.0017x over previous
#include <cuda_runtime.h>
#include <cuda_bf16.h>

// IoUMetricLoss: pred_label fp32 [8,19,512,1024], label int32 [8,512,1024]
// out: scalar fp32 = 1 - nanmean(IoU per class), all-NaN -> 0.5
//
// R9: confusion-matrix accumulation. R3 was co-saturated: 2 smem atomics
// per pixel = 0.54 lane-ops/cyc/SM vs the 0.5 ATOMS spread-addr cap.
// One CM[label*19+pred] atomic per pixel halves that to 0.27/cyc;
// area_label/pred/intersect are row/col/diagonal sums in the finalize.
// Grid/body otherwise identical to the proven R3 kernel.

#define NUM_CLASSES 19
#define CM_BINS (NUM_CLASSES * NUM_CLASSES)   // 361
#define HW_SHIFT 19                  // 512*1024 = 2^19
#define HW (1 << HW_SHIFT)
#define TOTAL_PIX (8 * HW)           // 4194304
#define VEC_GROUPS (TOTAL_PIX / 4)   // 1048576
#define HIST_BLOCK 256
#define WARPS_PER_BLOCK (HIST_BLOCK / 32)
#define GRID_BLOCKS (VEC_GROUPS / HIST_BLOCK)   // 4096

// Global state (no cudaMalloc allowed). Statically zero; the finalizing
// block re-zeros everything so each graph replay sees clean state.
__device__ unsigned int g_cm[CM_BINS];
__device__ unsigned int g_done;

__device__ __forceinline__ void amax_step(float v, float& bv, int& bi, int c) {
    float m = fmaxf(bv, v);
    bi = (v > bv) ? c : bi;
    bv = m;
}

__global__ void __launch_bounds__(HIST_BLOCK)
iou_fused_kernel(const float* __restrict__ pred,
                 const int* __restrict__ label,
                 float* __restrict__ out) {
    __shared__ unsigned int s_cm[WARPS_PER_BLOCK][CM_BINS];
    __shared__ int          s_is_last;

    const int tid  = threadIdx.x;
    const int warp = tid >> 5;
    const int lane = tid & 31;

    // zero this warp's private confusion matrix (361 bins)
    #pragma unroll
    for (int i = lane; i < CM_BINS; i += 32)
        s_cm[warp][i] = 0u;
    __syncwarp();

    const unsigned t  = blockIdx.x * blockDim.x + tid;   // 0..VEC_GROUPS-1
    const unsigned P  = t << 2;                 // first of 4 consecutive pixels
    const unsigned b  = P >> HW_SHIFT;          // batch index
    const unsigned hw = P & (HW - 1);

    const float* base = pred + ((size_t)b * NUM_CLASSES << HW_SHIFT) + hw;

    // label first — independent stream
    int4 lv = __ldcs((const int4*)(label + P));

    // argmax over 19 classes for 4 pixels
    float4 bv = __ldcs((const float4*)base);
    int i0 = 0, i1 = 0, i2 = 0, i3 = 0;
    #pragma unroll
    for (int c = 1; c < NUM_CLASSES; c++) {
        float4 v = __ldcs((const float4*)(base + ((size_t)c << HW_SHIFT)));
        amax_step(v.x, bv.x, i0, c);
        amax_step(v.y, bv.y, i1, c);
        amax_step(v.z, bv.z, i2, c);
        amax_step(v.w, bv.w, i3, c);
    }

    // ONE smem atomic per pixel: confusion-matrix bin label*19 + pred
    #define ACC(l, i)                                                          \
        if ((l) >= 0)                                                          \
            atomicAdd(&s_cm[warp][(l) * NUM_CLASSES + (i)], 1u);
    ACC(lv.x, i0); ACC(lv.y, i1); ACC(lv.z, i2); ACC(lv.w, i3);
    #undef ACC

    __syncthreads();

    // block reduce: sum the 8 warp copies, one global atomic per bin
    for (int bin = tid; bin < CM_BINS; bin += HIST_BLOCK) {
        unsigned int s = 0u;
        #pragma unroll
        for (int w = 0; w < WARPS_PER_BLOCK; w++)
            s += s_cm[w][bin];
        if (s) atomicAdd(&g_cm[bin], s);
    }
    __syncthreads();

    // last-block-done finalize + full state reset
    if (tid == 0) {
        __threadfence();
        unsigned prev = atomicAdd(&g_done, 1u);
        s_is_last = (prev == gridDim.x - 1);
    }
    __syncthreads();
    if (!s_is_last) return;

    __shared__ float s_loss;
    if (tid < 32) {
        const int c = tid;
        float iou_sum = 0.0f;
        int   valid   = 0;
        if (c < NUM_CLASSES) {
            unsigned long long lab = 0, pr = 0;
            #pragma unroll
            for (int k = 0; k < NUM_CLASSES; k++) {
                lab += g_cm[c * NUM_CLASSES + k];   // row sum: area_label
                pr  += g_cm[k * NUM_CLASSES + c];   // col sum: area_pred
            }
            unsigned long long inter = g_cm[c * NUM_CLASSES + c];
            unsigned long long uni   = lab + pr - inter;
            if (uni > 0ULL) {
                iou_sum = (float)inter / (float)uni;
                valid   = 1;
            }
            // uni == 0 -> 0/0 = NaN in reference, excluded by nanmean
        }
        #pragma unroll
        for (int o = 16; o > 0; o >>= 1) {
            iou_sum += __shfl_down_sync(0xFFFFFFFFu, iou_sum, o);
            valid   += __shfl_down_sync(0xFFFFFFFFu, valid, o);
        }
        if (c == 0)
            s_loss = (valid > 0) ? (1.0f - iou_sum / (float)valid) : 0.5f;
    }
    __syncthreads();
    // reset global state for the next graph replay, then emit
    for (int bin = tid; bin < CM_BINS; bin += HIST_BLOCK)
        g_cm[bin] = 0u;
    if (tid == 0) {
        g_done = 0u;
        *out = s_loss;
    }
}

extern "C" void kernel_launch(void* const* d_in, const int* in_sizes, int n_in,
                              void* d_out, int out_size) {
    // pred = 79,691,776 elems; label = 4,194,304 (resolve by size).
    const float* pred;
    const int*   label;
    if (in_sizes[0] >= in_sizes[1]) {
        pred  = (const float*)d_in[0];
        label = (const int*)d_in[1];
    } else {
        pred  = (const float*)d_in[1];
        label = (const int*)d_in[0];
    }
    float* out = (float*)d_out;

    iou_fused_kernel<<<GRID_BLOCKS, HIST_BLOCK>>>(pred, label, out);
}

// round 10
// speedup vs baseline: 1.1519x; 1.1499x over previous
#include <cuda_runtime.h>
#include <cuda_bf16.h>

// IoUMetricLoss: pred_label fp32 [8,19,512,1024], label int32 [8,512,1024]
// out: scalar fp32 = 1 - nanmean(IoU per class), all-NaN -> 0.5
//
// R10: split kernels. A = pure-streaming argmax (no atomics/smem; packed
// uint8 indices to __device__ scratch) to test whether a clean LDG stream
// exceeds the 5.77 TB/s plateau every fused variant hit. B = tiny
// histogram over labels + indices (indices L2-hot), confusion-matrix
// single atomic per pixel, fused last-block finalize + state reset.

#define NUM_CLASSES 19
#define CM_BINS (NUM_CLASSES * NUM_CLASSES)   // 361
#define HW_SHIFT 19                  // 512*1024 = 2^19
#define HW (1 << HW_SHIFT)
#define TOTAL_PIX (8 * HW)           // 4194304
#define VEC_GROUPS (TOTAL_PIX / 4)   // 1048576
#define A_BLOCK 256
#define A_GRID (VEC_GROUPS / A_BLOCK)          // 4096
#define B_BLOCK 256
#define B_GROUPS_PER_THREAD 4                  // 16 px/thread
#define B_GRID (VEC_GROUPS / (B_BLOCK * B_GROUPS_PER_THREAD))  // 1024
#define B_WARPS (B_BLOCK / 32)

// Scratch + accumulators (no cudaMalloc allowed). g_idx: 4 packed uint8
// argmax indices per vec-group. g_cm statically zero; B's finalizer
// re-zeros it so every graph replay sees clean state.
__device__ unsigned int g_idx[VEC_GROUPS];     // 4 MB scratch
__device__ unsigned int g_cm[CM_BINS];
__device__ unsigned int g_done;

__device__ __forceinline__ void amax_step(float v, float& bv, int& bi, int c) {
    float m = fmaxf(bv, v);
    bi = (v > bv) ? c : bi;
    bv = m;
}

// ---------- Kernel A: pure streaming argmax ----------
__global__ void __launch_bounds__(A_BLOCK)
iou_argmax_kernel(const float* __restrict__ pred) {
    const unsigned t  = blockIdx.x * A_BLOCK + threadIdx.x;  // vec-group id
    const unsigned P  = t << 2;
    const unsigned b  = P >> HW_SHIFT;
    const unsigned hw = P & (HW - 1);

    const float* base = pred + ((size_t)b * NUM_CLASSES << HW_SHIFT) + hw;

    float4 bv = __ldcs((const float4*)base);
    int i0 = 0, i1 = 0, i2 = 0, i3 = 0;
    #pragma unroll
    for (int c = 1; c < NUM_CLASSES; c++) {
        float4 v = __ldcs((const float4*)(base + ((size_t)c << HW_SHIFT)));
        amax_step(v.x, bv.x, i0, c);
        amax_step(v.y, bv.y, i1, c);
        amax_step(v.z, bv.z, i2, c);
        amax_step(v.w, bv.w, i3, c);
    }
    // default-cached store: B reads this right after -> L2 hit
    g_idx[t] = (unsigned)i0 | ((unsigned)i1 << 8) |
               ((unsigned)i2 << 16) | ((unsigned)i3 << 24);
}

// ---------- Kernel B: histogram + fused finalize ----------
__global__ void __launch_bounds__(B_BLOCK)
iou_hist_kernel(const int* __restrict__ label, float* __restrict__ out) {
    __shared__ unsigned int s_cm[B_WARPS][CM_BINS];
    __shared__ int          s_is_last;
    __shared__ float        s_loss;

    const int tid  = threadIdx.x;
    const int warp = tid >> 5;
    const int lane = tid & 31;

    #pragma unroll
    for (int i = lane; i < CM_BINS; i += 32)
        s_cm[warp][i] = 0u;
    __syncwarp();

    // this thread's 4 consecutive vec-groups (16 px)
    const unsigned g0 = (blockIdx.x * B_BLOCK + tid) * B_GROUPS_PER_THREAD;

    // packed argmax indices: one 16B load (L2-hot)
    uint4 iv = *(const uint4*)(g_idx + g0);
    unsigned packed[4] = {iv.x, iv.y, iv.z, iv.w};

    #pragma unroll
    for (int k = 0; k < 4; k++) {
        int4 lv = __ldcs((const int4*)(label + ((size_t)(g0 + k) << 2)));
        unsigned pk = packed[k];
        int l0 = lv.x, l1 = lv.y, l2 = lv.z, l3 = lv.w;
        int p0 = pk & 0xFF, p1 = (pk >> 8) & 0xFF;
        int p2 = (pk >> 16) & 0xFF, p3 = (pk >> 24) & 0xFF;
        if (l0 >= 0) atomicAdd(&s_cm[warp][l0 * NUM_CLASSES + p0], 1u);
        if (l1 >= 0) atomicAdd(&s_cm[warp][l1 * NUM_CLASSES + p1], 1u);
        if (l2 >= 0) atomicAdd(&s_cm[warp][l2 * NUM_CLASSES + p2], 1u);
        if (l3 >= 0) atomicAdd(&s_cm[warp][l3 * NUM_CLASSES + p3], 1u);
    }
    __syncthreads();

    // block reduce -> global CM
    for (int bin = tid; bin < CM_BINS; bin += B_BLOCK) {
        unsigned s = 0u;
        #pragma unroll
        for (int w = 0; w < B_WARPS; w++) s += s_cm[w][bin];
        if (s) atomicAdd(&g_cm[bin], s);
    }
    __syncthreads();

    if (tid == 0) {
        __threadfence();
        unsigned prev = atomicAdd(&g_done, 1u);
        s_is_last = (prev == gridDim.x - 1);
    }
    __syncthreads();
    if (!s_is_last) return;

    if (tid < 32) {
        const int c = tid;
        float iou_sum = 0.0f;
        int   valid   = 0;
        if (c < NUM_CLASSES) {
            unsigned long long lab = 0, pr = 0;
            #pragma unroll
            for (int k = 0; k < NUM_CLASSES; k++) {
                lab += g_cm[c * NUM_CLASSES + k];   // row sum: area_label
                pr  += g_cm[k * NUM_CLASSES + c];   // col sum: area_pred
            }
            unsigned long long inter = g_cm[c * NUM_CLASSES + c];
            unsigned long long uni   = lab + pr - inter;
            if (uni > 0ULL) {
                iou_sum = (float)inter / (float)uni;
                valid   = 1;
            }
            // uni == 0 -> 0/0 = NaN in reference, excluded by nanmean
        }
        #pragma unroll
        for (int o = 16; o > 0; o >>= 1) {
            iou_sum += __shfl_down_sync(0xFFFFFFFFu, iou_sum, o);
            valid   += __shfl_down_sync(0xFFFFFFFFu, valid, o);
        }
        if (c == 0)
            s_loss = (valid > 0) ? (1.0f - iou_sum / (float)valid) : 0.5f;
    }
    __syncthreads();
    // reset global state for the next graph replay, then emit
    for (int bin = tid; bin < CM_BINS; bin += B_BLOCK)
        g_cm[bin] = 0u;
    if (tid == 0) {
        g_done = 0u;
        *out = s_loss;
    }
}

extern "C" void kernel_launch(void* const* d_in, const int* in_sizes, int n_in,
                              void* d_out, int out_size) {
    // pred = 79,691,776 elems; label = 4,194,304 (resolve by size).
    const float* pred;
    const int*   label;
    if (in_sizes[0] >= in_sizes[1]) {
        pred  = (const float*)d_in[0];
        label = (const int*)d_in[1];
    } else {
        pred  = (const float*)d_in[1];
        label = (const int*)d_in[0];
    }
    float* out = (float*)d_out;

    iou_argmax_kernel<<<A_GRID, A_BLOCK>>>(pred);
    iou_hist_kernel<<<B_GRID, B_BLOCK>>>(label, out);
}